// round 12
// baseline (speedup 1.0000x reference)
#include <cuda_runtime.h>

#define FULLMASK 0xFFFFFFFFu

namespace {
constexpr int P_GRID  = 4096;   // patches (64x64)
constexpr int NROWS   = 8192;   // B * P = 2 * 4096
constexpr int HDIM    = 32;
constexpr int T_TOTAL = 59;
constexpr int T_OBS   = 10;
constexpr int KSTR    = 36;     // padded row stride for q/k/v (34 -> 36)

constexpr int NBLOCKS  = 148;
constexpr int NWARPS   = 28;
constexpr int NTHREADS = NWARPS * 32;   // 896
}

// Double-buffered per-step q/k/v (ping-pong by step parity). ~7 MB static.
__device__ float g_q[2][NROWS * KSTR];
__device__ float g_k[2][NROWS * KSTR];
__device__ float g_v[2][NROWS * KSTR];

// Software grid barrier state (zero-initialized; count returns to 0 each barrier).
__device__ unsigned g_bar_count;
__device__ unsigned g_bar_epoch;

struct Smem {
    float Wx[32 * 33];    // W_x2h, rows padded to 33 (conflict-free)
    float Wh[32 * 33];    // W_h2h
    float Wf2[32 * 33];   // W_fc2
    float Wsa[32 * 35];   // W_fcsa [32][34] padded to 35
    float Wout[34 * 35];  // W_out  [34][34] padded to 35
    float Win[102 * 35];  // W_in   [102][34] padded to 35
    float b_h[32];        // b_x2h + b_h2h
    float b_in[102];
    float b_out[34];
    float b_sa[32];
    float b_f2[32];
    float lng[32];
    float lnb[32];
};

__device__ __forceinline__ void grid_barrier() {
    __threadfence();          // each thread makes its own prior writes device-visible
    __syncthreads();
    if (threadIdx.x == 0) {
        volatile unsigned* ep = &g_bar_epoch;
        unsigned e = *ep;     // epoch cannot advance until this block arrives
        unsigned t = atomicAdd(&g_bar_count, 1u);
        if (t == (unsigned)(NBLOCKS - 1)) {
            g_bar_count = 0u;
            __threadfence();
            atomicAdd(&g_bar_epoch, 1u);
        } else {
            while (*ep == e) { }
        }
        __threadfence();
    }
    __syncthreads();
}

__device__ __forceinline__ float warp_sum(float v) {
    v += __shfl_xor_sync(FULLMASK, v, 16);
    v += __shfl_xor_sync(FULLMASK, v, 8);
    v += __shfl_xor_sync(FULLMASK, v, 4);
    v += __shfl_xor_sync(FULLMASK, v, 2);
    v += __shfl_xor_sync(FULLMASK, v, 1);
    return v;
}

// Phase A: h_pre = tanh(x*Wx^T + h*Wh^T + b); qkv = [h_pre, r/64, c/64] @ W_in^T + b_in.
// Publishes q,k,v for row n into buffer `buf`. Returns h_pre (lane holds element `lane`).
__device__ __forceinline__ float phaseA(const Smem& sm, int n, int buf,
                                        float xin, float h, int lane) {
    // Fused RNN matvec (lane j computes output j)
    float acc = sm.b_h[lane];
    const float* wx = sm.Wx + lane * 33;
    const float* wh = sm.Wh + lane * 33;
#pragma unroll
    for (int i = 0; i < 32; i++) {
        float xi = __shfl_sync(FULLMASK, xin, i);
        float hi = __shfl_sync(FULLMASK, h, i);
        acc = fmaf(xi, wx[i], acc);
        acc = fmaf(hi, wh[i], acc);
    }
    float hp = tanhf(acc);

    int p = n & (P_GRID - 1);
    float cr = (float)(p >> 6) * (1.0f / 64.0f);
    float cc = (float)(p & 63) * (1.0f / 64.0f);

    // qkv: lane j -> q[j], k[j], v[j]; lanes 26..31 handle tail rows {32,33,66,67,100,101}
    bool tl = (lane >= 26);
    int d = lane - 26;
    int trow = tl ? (32 + ((d >> 1) * 34) + (d & 1)) : 0;
    float aq = sm.b_in[lane];
    float ak = sm.b_in[34 + lane];
    float av = sm.b_in[68 + lane];
    float at = tl ? sm.b_in[trow] : 0.0f;
    const float* Wq = sm.Win + lane * 35;
    const float* Wk = sm.Win + (34 + lane) * 35;
    const float* Wv = sm.Win + (68 + lane) * 35;
    const float* Wt = sm.Win + trow * 35;
#pragma unroll
    for (int i = 0; i < 32; i++) {
        float hi = __shfl_sync(FULLMASK, hp, i);
        aq = fmaf(hi, Wq[i], aq);
        ak = fmaf(hi, Wk[i], ak);
        av = fmaf(hi, Wv[i], av);
        if (tl) at = fmaf(hi, Wt[i], at);
    }
    aq = fmaf(cr, Wq[32], aq); aq = fmaf(cc, Wq[33], aq);
    ak = fmaf(cr, Wk[32], ak); ak = fmaf(cc, Wk[33], ak);
    av = fmaf(cr, Wv[32], av); av = fmaf(cc, Wv[33], av);
    if (tl) { at = fmaf(cr, Wt[32], at); at = fmaf(cc, Wt[33], at); }

    float* qb = g_q[buf] + n * KSTR;
    float* kb = g_k[buf] + n * KSTR;
    float* vb = g_v[buf] + n * KSTR;
    __stcg(qb + lane, aq);
    __stcg(kb + lane, ak);
    __stcg(vb + lane, av);
    if (tl) {
        float* dst = (d < 2 ? qb : (d < 4 ? kb : vb)) + 32 + (d & 1);
        __stcg(dst, at);
    }
    return hp;
}

// Phase B: 9-neighbor attention + out-proj + fcsa residual + fc2 + layernorm.
__device__ __forceinline__ void phaseB(const Smem& sm, int n, int buf, float hp,
                                       float* h_out, float* pred_out,
                                       float* __restrict__ out_t, int lane) {
    int p = n & (P_GRID - 1);
    int b_off = n - p;
    int r = p >> 6, c = p & 63;
    int rs = (r == 0) - (r == 63);
    int cs = (c == 0) - (c == 63);
    int base = b_off + p + rs * 64 + cs;   // row of shifted-center slot (l=4)

    const float* qrow = g_q[buf] + base * KSTR;
    float qj = __ldcg(qrow + lane);
    float qt = (lane < 2) ? __ldcg(qrow + 32 + lane) : 0.0f;
    float q32 = __shfl_sync(FULLMASK, qt, 0);
    float q33 = __shfl_sync(FULLMASK, qt, 1);

    const int OFF[9] = {-65, -64, -63, -1, 0, 1, 63, 64, 65};
    float s[9];
#pragma unroll
    for (int l = 0; l < 9; l++) {
        const float* kr = g_k[buf] + (base + OFF[l]) * KSTR;
        float pr = qj * __ldcg(kr + lane);
        if (lane < 2) {
            float kt = __ldcg(kr + 32 + lane);
            pr = fmaf((lane == 0) ? q32 : q33, kt, pr);
        }
        s[l] = warp_sum(pr);
    }
    const float SCALE = 0.17149858514250882f;  // 1/sqrt(34)
    float mx = s[0];
#pragma unroll
    for (int l = 1; l < 9; l++) mx = fmaxf(mx, s[l]);
    float wsum = 0.0f;
#pragma unroll
    for (int l = 0; l < 9; l++) { s[l] = __expf((s[l] - mx) * SCALE); wsum += s[l]; }
    float rinv = 1.0f / wsum;

    float oj = 0.0f, ot = 0.0f;
#pragma unroll
    for (int l = 0; l < 9; l++) {
        const float* vr = g_v[buf] + (base + OFF[l]) * KSTR;
        oj = fmaf(s[l], __ldcg(vr + lane), oj);
        if (lane < 2) ot = fmaf(s[l], __ldcg(vr + 32 + lane), ot);
    }
    oj *= rinv; ot *= rinv;
    float o32 = __shfl_sync(FULLMASK, ot, 0);
    float o33 = __shfl_sync(FULLMASK, ot, 1);

    // out-projection: 34 -> 34 (tail rows 32,33 on lanes 30,31)
    bool t2 = (lane >= 30);
    int trow2 = t2 ? (32 + (lane - 30)) : 0;
    float ao = sm.b_out[lane];
    float aot = t2 ? sm.b_out[trow2] : 0.0f;
    const float* Wo  = sm.Wout + lane * 35;
    const float* Wot = sm.Wout + trow2 * 35;
#pragma unroll
    for (int i = 0; i < 32; i++) {
        float oi = __shfl_sync(FULLMASK, oj, i);
        ao = fmaf(oi, Wo[i], ao);
        if (t2) aot = fmaf(oi, Wot[i], aot);
    }
    ao = fmaf(o32, Wo[32], ao); ao = fmaf(o33, Wo[33], ao);
    if (t2) { aot = fmaf(o32, Wot[32], aot); aot = fmaf(o33, Wot[33], aot); }
    float ao32 = __shfl_sync(FULLMASK, aot, 30);
    float ao33 = __shfl_sync(FULLMASK, aot, 31);

    // fcsa residual: h = h_pre + ao @ W_fcsa^T + b_fcsa
    float dh = sm.b_sa[lane];
    const float* Ws = sm.Wsa + lane * 35;
#pragma unroll
    for (int i = 0; i < 32; i++) {
        float ai = __shfl_sync(FULLMASK, ao, i);
        dh = fmaf(ai, Ws[i], dh);
    }
    dh = fmaf(ao32, Ws[32], dh);
    dh = fmaf(ao33, Ws[33], dh);
    float h = hp + dh;

    // fc2 + layernorm
    float y = sm.b_f2[lane];
    const float* Wf = sm.Wf2 + lane * 33;
#pragma unroll
    for (int i = 0; i < 32; i++) {
        float hi = __shfl_sync(FULLMASK, h, i);
        y = fmaf(hi, Wf[i], y);
    }
    float mu = warp_sum(y) * (1.0f / 32.0f);
    float dv = y - mu;
    float var = warp_sum(dv * dv) * (1.0f / 32.0f);
    float pred = dv * rsqrtf(var + 1e-5f) * sm.lng[lane] + sm.lnb[lane];

    out_t[n * HDIM + lane] = pred;
    *h_out = h;
    *pred_out = pred;
}

__global__ void __launch_bounds__(NTHREADS, 1)
rnn_persistent_kernel(const float* __restrict__ x,
                      const float* __restrict__ Wx, const float* __restrict__ bx,
                      const float* __restrict__ Wh, const float* __restrict__ bh,
                      const float* __restrict__ Wf2, const float* __restrict__ bf2,
                      const float* __restrict__ lng, const float* __restrict__ lnb,
                      const float* __restrict__ Wsa, const float* __restrict__ bsa,
                      const float* __restrict__ Win, const float* __restrict__ bin,
                      const float* __restrict__ Wout, const float* __restrict__ bout,
                      float* __restrict__ out) {
    __shared__ Smem sm;
    int tid = threadIdx.x;

    for (int idx = tid; idx < 32 * 32; idx += NTHREADS) {
        int rr = idx >> 5, ii = idx & 31;
        sm.Wx[rr * 33 + ii]  = Wx[idx];
        sm.Wh[rr * 33 + ii]  = Wh[idx];
        sm.Wf2[rr * 33 + ii] = Wf2[idx];
    }
    for (int idx = tid; idx < 32 * 34; idx += NTHREADS) {
        int rr = idx / 34, ii = idx % 34;
        sm.Wsa[rr * 35 + ii] = Wsa[idx];
    }
    for (int idx = tid; idx < 34 * 34; idx += NTHREADS) {
        int rr = idx / 34, ii = idx % 34;
        sm.Wout[rr * 35 + ii] = Wout[idx];
    }
    for (int idx = tid; idx < 102 * 34; idx += NTHREADS) {
        int rr = idx / 34, ii = idx % 34;
        sm.Win[rr * 35 + ii] = Win[idx];
    }
    if (tid < 32) {
        sm.b_h[tid]  = bx[tid] + bh[tid];
        sm.b_sa[tid] = bsa[tid];
        sm.b_f2[tid] = bf2[tid];
        sm.lng[tid]  = lng[tid];
        sm.lnb[tid]  = lnb[tid];
    }
    for (int idx = tid; idx < 102; idx += NTHREADS) sm.b_in[idx] = bin[idx];
    if (tid < 34) sm.b_out[tid] = bout[tid];
    __syncthreads();

    int wid = tid >> 5, lane = tid & 31;
    int gw = blockIdx.x * NWARPS + wid;
    int n0 = gw * 2;
    bool active = (n0 < NROWS);

    float h[2]    = {0.0f, 0.0f};
    float hp[2]   = {0.0f, 0.0f};
    float pred[2] = {0.0f, 0.0f};

    // Phase A for t = 0 (input = x[0], h = 0)
    if (active) {
#pragma unroll
        for (int rr = 0; rr < 2; rr++) {
            float xin = x[(n0 + rr) * HDIM + lane];
            hp[rr] = phaseA(sm, n0 + rr, 0, xin, h[rr], lane);
        }
    }

    for (int t = 0; t < T_TOTAL; t++) {
        grid_barrier();   // q/k/v(t) of all rows now visible
        int buf = t & 1;
        if (active) {
            float* out_t = out + (size_t)t * NROWS * HDIM;
#pragma unroll
            for (int rr = 0; rr < 2; rr++) {
                phaseB(sm, n0 + rr, buf, hp[rr], &h[rr], &pred[rr], out_t, lane);
            }
            if (t < T_TOTAL - 1) {
#pragma unroll
                for (int rr = 0; rr < 2; rr++) {
                    float xin = (t + 1 < T_OBS)
                                    ? x[(size_t)(t + 1) * NROWS * HDIM + (n0 + rr) * HDIM + lane]
                                    : pred[rr];
                    hp[rr] = phaseA(sm, n0 + rr, buf ^ 1, xin, h[rr], lane);
                }
            }
        }
    }
}

extern "C" void kernel_launch(void* const* d_in, const int* in_sizes, int n_in,
                              void* d_out, int out_size) {
    (void)in_sizes; (void)n_in; (void)out_size;
    rnn_persistent_kernel<<<NBLOCKS, NTHREADS>>>(
        (const float*)d_in[0],   // x
        (const float*)d_in[1],   // W_x2h
        (const float*)d_in[2],   // b_x2h
        (const float*)d_in[3],   // W_h2h
        (const float*)d_in[4],   // b_h2h
        (const float*)d_in[5],   // W_fc2
        (const float*)d_in[6],   // b_fc2
        (const float*)d_in[7],   // ln_g
        (const float*)d_in[8],   // ln_b
        (const float*)d_in[9],   // W_fcsa
        (const float*)d_in[10],  // b_fcsa
        (const float*)d_in[11],  // W_in
        (const float*)d_in[12],  // b_in
        (const float*)d_in[13],  // W_out
        (const float*)d_in[14],  // b_out
        (float*)d_out);
}

// round 13
// speedup vs baseline: 1.0022x; 1.0022x over previous
#include <cuda_runtime.h>

#define FULLMASK 0xFFFFFFFFu

namespace {
constexpr int P_GRID  = 4096;   // patches (64x64)
constexpr int NROWS   = 8192;   // B * P = 2 * 4096
constexpr int HDIM    = 32;
constexpr int T_TOTAL = 59;
constexpr int T_OBS   = 10;
constexpr int KSTR    = 36;     // padded row stride for q/k/v (34 -> 36)

constexpr int NBLOCKS  = 148;
constexpr int NWARPS   = 28;
constexpr int NTHREADS = NWARPS * 32;   // 896
}

// Double-buffered per-step q/k/v (ping-pong by step parity). ~7 MB static.
__device__ float g_q[2][NROWS * KSTR];
__device__ float g_k[2][NROWS * KSTR];
__device__ float g_v[2][NROWS * KSTR];

// Software grid barrier state (zero-initialized; count returns to 0 each barrier).
__device__ unsigned g_bar_count;
__device__ unsigned g_bar_epoch;

struct Smem {
    float Wx[32 * 33];    // W_x2h, rows padded to 33 (conflict-free)
    float Wh[32 * 33];    // W_h2h
    float Wf2[32 * 33];   // W_fc2
    float Wsa[32 * 35];   // W_fcsa [32][34] padded to 35
    float Wout[34 * 35];  // W_out  [34][34] padded to 35
    float Win[102 * 35];  // W_in   [102][34] padded to 35
    float b_h[32];        // b_x2h + b_h2h
    float b_in[102];
    float b_out[34];
    float b_sa[32];
    float b_f2[32];
    float lng[32];
    float lnb[32];
};

__device__ __forceinline__ void grid_barrier() {
    __threadfence();          // each thread makes its own prior writes device-visible
    __syncthreads();
    if (threadIdx.x == 0) {
        volatile unsigned* ep = &g_bar_epoch;
        unsigned e = *ep;     // epoch cannot advance until this block arrives
        unsigned t = atomicAdd(&g_bar_count, 1u);
        if (t == (unsigned)(NBLOCKS - 1)) {
            g_bar_count = 0u;
            __threadfence();
            atomicAdd(&g_bar_epoch, 1u);
        } else {
            while (*ep == e) { }
        }
        __threadfence();
    }
    __syncthreads();
}

__device__ __forceinline__ float warp_sum(float v) {
    v += __shfl_xor_sync(FULLMASK, v, 16);
    v += __shfl_xor_sync(FULLMASK, v, 8);
    v += __shfl_xor_sync(FULLMASK, v, 4);
    v += __shfl_xor_sync(FULLMASK, v, 2);
    v += __shfl_xor_sync(FULLMASK, v, 1);
    return v;
}

// Phase A: h_pre = tanh(x*Wx^T + h*Wh^T + b); qkv = [h_pre, r/64, c/64] @ W_in^T + b_in.
// Publishes q,k,v for row n into buffer `buf`. Returns h_pre (lane holds element `lane`).
__device__ __forceinline__ float phaseA(const Smem& sm, int n, int buf,
                                        float xin, float h, int lane) {
    // Fused RNN matvec (lane j computes output j)
    float acc = sm.b_h[lane];
    const float* wx = sm.Wx + lane * 33;
    const float* wh = sm.Wh + lane * 33;
#pragma unroll
    for (int i = 0; i < 32; i++) {
        float xi = __shfl_sync(FULLMASK, xin, i);
        float hi = __shfl_sync(FULLMASK, h, i);
        acc = fmaf(xi, wx[i], acc);
        acc = fmaf(hi, wh[i], acc);
    }
    float hp = tanhf(acc);

    int p = n & (P_GRID - 1);
    float cr = (float)(p >> 6) * (1.0f / 64.0f);
    float cc = (float)(p & 63) * (1.0f / 64.0f);

    // qkv: lane j -> q[j], k[j], v[j]; lanes 26..31 handle tail rows {32,33,66,67,100,101}
    bool tl = (lane >= 26);
    int d = lane - 26;
    int trow = tl ? (32 + ((d >> 1) * 34) + (d & 1)) : 0;
    float aq = sm.b_in[lane];
    float ak = sm.b_in[34 + lane];
    float av = sm.b_in[68 + lane];
    float at = tl ? sm.b_in[trow] : 0.0f;
    const float* Wq = sm.Win + lane * 35;
    const float* Wk = sm.Win + (34 + lane) * 35;
    const float* Wv = sm.Win + (68 + lane) * 35;
    const float* Wt = sm.Win + trow * 35;
#pragma unroll
    for (int i = 0; i < 32; i++) {
        float hi = __shfl_sync(FULLMASK, hp, i);
        aq = fmaf(hi, Wq[i], aq);
        ak = fmaf(hi, Wk[i], ak);
        av = fmaf(hi, Wv[i], av);
        if (tl) at = fmaf(hi, Wt[i], at);
    }
    aq = fmaf(cr, Wq[32], aq); aq = fmaf(cc, Wq[33], aq);
    ak = fmaf(cr, Wk[32], ak); ak = fmaf(cc, Wk[33], ak);
    av = fmaf(cr, Wv[32], av); av = fmaf(cc, Wv[33], av);
    if (tl) { at = fmaf(cr, Wt[32], at); at = fmaf(cc, Wt[33], at); }

    float* qb = g_q[buf] + n * KSTR;
    float* kb = g_k[buf] + n * KSTR;
    float* vb = g_v[buf] + n * KSTR;
    __stcg(qb + lane, aq);
    __stcg(kb + lane, ak);
    __stcg(vb + lane, av);
    if (tl) {
        float* dst = (d < 2 ? qb : (d < 4 ? kb : vb)) + 32 + (d & 1);
        __stcg(dst, at);
    }
    return hp;
}

// Phase B: 9-neighbor attention + out-proj + fcsa residual + fc2 + layernorm.
__device__ __forceinline__ void phaseB(const Smem& sm, int n, int buf, float hp,
                                       float* h_out, float* pred_out,
                                       float* __restrict__ out_t, int lane) {
    int p = n & (P_GRID - 1);
    int b_off = n - p;
    int r = p >> 6, c = p & 63;
    int rs = (r == 0) - (r == 63);
    int cs = (c == 0) - (c == 63);
    int base = b_off + p + rs * 64 + cs;   // row of shifted-center slot (l=4)

    const float* qrow = g_q[buf] + base * KSTR;
    float qj = __ldcg(qrow + lane);
    float qt = (lane < 2) ? __ldcg(qrow + 32 + lane) : 0.0f;
    float q32 = __shfl_sync(FULLMASK, qt, 0);
    float q33 = __shfl_sync(FULLMASK, qt, 1);

    const int OFF[9] = {-65, -64, -63, -1, 0, 1, 63, 64, 65};
    float s[9];
#pragma unroll
    for (int l = 0; l < 9; l++) {
        const float* kr = g_k[buf] + (base + OFF[l]) * KSTR;
        float pr = qj * __ldcg(kr + lane);
        if (lane < 2) {
            float kt = __ldcg(kr + 32 + lane);
            pr = fmaf((lane == 0) ? q32 : q33, kt, pr);
        }
        s[l] = warp_sum(pr);
    }
    const float SCALE = 0.17149858514250882f;  // 1/sqrt(34)
    float mx = s[0];
#pragma unroll
    for (int l = 1; l < 9; l++) mx = fmaxf(mx, s[l]);
    float wsum = 0.0f;
#pragma unroll
    for (int l = 0; l < 9; l++) { s[l] = __expf((s[l] - mx) * SCALE); wsum += s[l]; }
    float rinv = 1.0f / wsum;

    float oj = 0.0f, ot = 0.0f;
#pragma unroll
    for (int l = 0; l < 9; l++) {
        const float* vr = g_v[buf] + (base + OFF[l]) * KSTR;
        oj = fmaf(s[l], __ldcg(vr + lane), oj);
        if (lane < 2) ot = fmaf(s[l], __ldcg(vr + 32 + lane), ot);
    }
    oj *= rinv; ot *= rinv;
    float o32 = __shfl_sync(FULLMASK, ot, 0);
    float o33 = __shfl_sync(FULLMASK, ot, 1);

    // out-projection: 34 -> 34 (tail rows 32,33 on lanes 30,31)
    bool t2 = (lane >= 30);
    int trow2 = t2 ? (32 + (lane - 30)) : 0;
    float ao = sm.b_out[lane];
    float aot = t2 ? sm.b_out[trow2] : 0.0f;
    const float* Wo  = sm.Wout + lane * 35;
    const float* Wot = sm.Wout + trow2 * 35;
#pragma unroll
    for (int i = 0; i < 32; i++) {
        float oi = __shfl_sync(FULLMASK, oj, i);
        ao = fmaf(oi, Wo[i], ao);
        if (t2) aot = fmaf(oi, Wot[i], aot);
    }
    ao = fmaf(o32, Wo[32], ao); ao = fmaf(o33, Wo[33], ao);
    if (t2) { aot = fmaf(o32, Wot[32], aot); aot = fmaf(o33, Wot[33], aot); }
    float ao32 = __shfl_sync(FULLMASK, aot, 30);
    float ao33 = __shfl_sync(FULLMASK, aot, 31);

    // fcsa residual: h = h_pre + ao @ W_fcsa^T + b_fcsa
    float dh = sm.b_sa[lane];
    const float* Ws = sm.Wsa + lane * 35;
#pragma unroll
    for (int i = 0; i < 32; i++) {
        float ai = __shfl_sync(FULLMASK, ao, i);
        dh = fmaf(ai, Ws[i], dh);
    }
    dh = fmaf(ao32, Ws[32], dh);
    dh = fmaf(ao33, Ws[33], dh);
    float h = hp + dh;

    // fc2 + layernorm
    float y = sm.b_f2[lane];
    const float* Wf = sm.Wf2 + lane * 33;
#pragma unroll
    for (int i = 0; i < 32; i++) {
        float hi = __shfl_sync(FULLMASK, h, i);
        y = fmaf(hi, Wf[i], y);
    }
    float mu = warp_sum(y) * (1.0f / 32.0f);
    float dv = y - mu;
    float var = warp_sum(dv * dv) * (1.0f / 32.0f);
    float pred = dv * rsqrtf(var + 1e-5f) * sm.lng[lane] + sm.lnb[lane];

    out_t[n * HDIM + lane] = pred;
    *h_out = h;
    *pred_out = pred;
}

__global__ void __launch_bounds__(NTHREADS, 1)
rnn_persistent_kernel(const float* __restrict__ x,
                      const float* __restrict__ Wx, const float* __restrict__ bx,
                      const float* __restrict__ Wh, const float* __restrict__ bh,
                      const float* __restrict__ Wf2, const float* __restrict__ bf2,
                      const float* __restrict__ lng, const float* __restrict__ lnb,
                      const float* __restrict__ Wsa, const float* __restrict__ bsa,
                      const float* __restrict__ Win, const float* __restrict__ bin,
                      const float* __restrict__ Wout, const float* __restrict__ bout,
                      float* __restrict__ out) {
    __shared__ Smem sm;
    int tid = threadIdx.x;

    for (int idx = tid; idx < 32 * 32; idx += NTHREADS) {
        int rr = idx >> 5, ii = idx & 31;
        sm.Wx[rr * 33 + ii]  = Wx[idx];
        sm.Wh[rr * 33 + ii]  = Wh[idx];
        sm.Wf2[rr * 33 + ii] = Wf2[idx];
    }
    for (int idx = tid; idx < 32 * 34; idx += NTHREADS) {
        int rr = idx / 34, ii = idx % 34;
        sm.Wsa[rr * 35 + ii] = Wsa[idx];
    }
    for (int idx = tid; idx < 34 * 34; idx += NTHREADS) {
        int rr = idx / 34, ii = idx % 34;
        sm.Wout[rr * 35 + ii] = Wout[idx];
    }
    for (int idx = tid; idx < 102 * 34; idx += NTHREADS) {
        int rr = idx / 34, ii = idx % 34;
        sm.Win[rr * 35 + ii] = Win[idx];
    }
    if (tid < 32) {
        sm.b_h[tid]  = bx[tid] + bh[tid];
        sm.b_sa[tid] = bsa[tid];
        sm.b_f2[tid] = bf2[tid];
        sm.lng[tid]  = lng[tid];
        sm.lnb[tid]  = lnb[tid];
    }
    for (int idx = tid; idx < 102; idx += NTHREADS) sm.b_in[idx] = bin[idx];
    if (tid < 34) sm.b_out[tid] = bout[tid];
    __syncthreads();

    int wid = tid >> 5, lane = tid & 31;
    int gw = blockIdx.x * NWARPS + wid;
    int n0 = gw * 2;
    bool active = (n0 < NROWS);

    float h[2]    = {0.0f, 0.0f};
    float hp[2]   = {0.0f, 0.0f};
    float pred[2] = {0.0f, 0.0f};

    // Phase A for t = 0 (input = x[0], h = 0)
    if (active) {
#pragma unroll
        for (int rr = 0; rr < 2; rr++) {
            float xin = x[(n0 + rr) * HDIM + lane];
            hp[rr] = phaseA(sm, n0 + rr, 0, xin, h[rr], lane);
        }
    }

    for (int t = 0; t < T_TOTAL; t++) {
        grid_barrier();   // q/k/v(t) of all rows now visible
        int buf = t & 1;
        if (active) {
            float* out_t = out + (size_t)t * NROWS * HDIM;
#pragma unroll
            for (int rr = 0; rr < 2; rr++) {
                phaseB(sm, n0 + rr, buf, hp[rr], &h[rr], &pred[rr], out_t, lane);
            }
            if (t < T_TOTAL - 1) {
#pragma unroll
                for (int rr = 0; rr < 2; rr++) {
                    float xin = (t + 1 < T_OBS)
                                    ? x[(size_t)(t + 1) * NROWS * HDIM + (n0 + rr) * HDIM + lane]
                                    : pred[rr];
                    hp[rr] = phaseA(sm, n0 + rr, buf ^ 1, xin, h[rr], lane);
                }
            }
        }
    }
}

extern "C" void kernel_launch(void* const* d_in, const int* in_sizes, int n_in,
                              void* d_out, int out_size) {
    (void)in_sizes; (void)n_in; (void)out_size;
    rnn_persistent_kernel<<<NBLOCKS, NTHREADS>>>(
        (const float*)d_in[0],   // x
        (const float*)d_in[1],   // W_x2h
        (const float*)d_in[2],   // b_x2h
        (const float*)d_in[3],   // W_h2h
        (const float*)d_in[4],   // b_h2h
        (const float*)d_in[5],   // W_fc2
        (const float*)d_in[6],   // b_fc2
        (const float*)d_in[7],   // ln_g
        (const float*)d_in[8],   // ln_b
        (const float*)d_in[9],   // W_fcsa
        (const float*)d_in[10],  // b_fcsa
        (const float*)d_in[11],  // W_in
        (const float*)d_in[12],  // b_in
        (const float*)d_in[13],  // W_out
        (const float*)d_in[14],  // b_out
        (float*)d_out);
}

// round 14
// speedup vs baseline: 1.0027x; 1.0005x over previous
#include <cuda_runtime.h>

#define FULLMASK 0xFFFFFFFFu

namespace {
constexpr int P_GRID  = 4096;   // patches (64x64)
constexpr int NROWS   = 8192;   // B * P = 2 * 4096
constexpr int HDIM    = 32;
constexpr int T_TOTAL = 59;
constexpr int T_OBS   = 10;
constexpr int KSTR    = 36;     // padded row stride for q/k/v (34 -> 36)

constexpr int NBLOCKS  = 148;
constexpr int NWARPS   = 28;
constexpr int NTHREADS = NWARPS * 32;   // 896
}

// Double-buffered per-step q/k/v (ping-pong by step parity). ~7 MB static.
__device__ float g_q[2][NROWS * KSTR];
__device__ float g_k[2][NROWS * KSTR];
__device__ float g_v[2][NROWS * KSTR];

// Software grid barrier state (zero-initialized; count returns to 0 each barrier).
__device__ unsigned g_bar_count;
__device__ unsigned g_bar_epoch;

struct Smem {
    float Wx[32 * 33];    // W_x2h, rows padded to 33 (conflict-free)
    float Wh[32 * 33];    // W_h2h
    float Wf2[32 * 33];   // W_fc2
    float Wsa[32 * 35];   // W_fcsa [32][34] padded to 35
    float Wout[34 * 35];  // W_out  [34][34] padded to 35
    float Win[102 * 35];  // W_in   [102][34] padded to 35
    float b_h[32];        // b_x2h + b_h2h
    float b_in[102];
    float b_out[34];
    float b_sa[32];
    float b_f2[32];
    float lng[32];
    float lnb[32];
};

__device__ __forceinline__ void grid_barrier() {
    __threadfence();          // each thread makes its own prior writes device-visible
    __syncthreads();
    if (threadIdx.x == 0) {
        volatile unsigned* ep = &g_bar_epoch;
        unsigned e = *ep;     // epoch cannot advance until this block arrives
        unsigned t = atomicAdd(&g_bar_count, 1u);
        if (t == (unsigned)(NBLOCKS - 1)) {
            g_bar_count = 0u;
            __threadfence();
            atomicAdd(&g_bar_epoch, 1u);
        } else {
            while (*ep == e) { }
        }
        __threadfence();
    }
    __syncthreads();
}

__device__ __forceinline__ float warp_sum(float v) {
    v += __shfl_xor_sync(FULLMASK, v, 16);
    v += __shfl_xor_sync(FULLMASK, v, 8);
    v += __shfl_xor_sync(FULLMASK, v, 4);
    v += __shfl_xor_sync(FULLMASK, v, 2);
    v += __shfl_xor_sync(FULLMASK, v, 1);
    return v;
}

// Phase A: h_pre = tanh(x*Wx^T + h*Wh^T + b); qkv = [h_pre, r/64, c/64] @ W_in^T + b_in.
// Publishes q,k,v for row n into buffer `buf`. Returns h_pre (lane holds element `lane`).
__device__ __forceinline__ float phaseA(const Smem& sm, int n, int buf,
                                        float xin, float h, int lane) {
    // Fused RNN matvec (lane j computes output j)
    float acc = sm.b_h[lane];
    const float* wx = sm.Wx + lane * 33;
    const float* wh = sm.Wh + lane * 33;
#pragma unroll
    for (int i = 0; i < 32; i++) {
        float xi = __shfl_sync(FULLMASK, xin, i);
        float hi = __shfl_sync(FULLMASK, h, i);
        acc = fmaf(xi, wx[i], acc);
        acc = fmaf(hi, wh[i], acc);
    }
    float hp = tanhf(acc);

    int p = n & (P_GRID - 1);
    float cr = (float)(p >> 6) * (1.0f / 64.0f);
    float cc = (float)(p & 63) * (1.0f / 64.0f);

    // qkv: lane j -> q[j], k[j], v[j]; lanes 26..31 handle tail rows {32,33,66,67,100,101}
    bool tl = (lane >= 26);
    int d = lane - 26;
    int trow = tl ? (32 + ((d >> 1) * 34) + (d & 1)) : 0;
    float aq = sm.b_in[lane];
    float ak = sm.b_in[34 + lane];
    float av = sm.b_in[68 + lane];
    float at = tl ? sm.b_in[trow] : 0.0f;
    const float* Wq = sm.Win + lane * 35;
    const float* Wk = sm.Win + (34 + lane) * 35;
    const float* Wv = sm.Win + (68 + lane) * 35;
    const float* Wt = sm.Win + trow * 35;
#pragma unroll
    for (int i = 0; i < 32; i++) {
        float hi = __shfl_sync(FULLMASK, hp, i);
        aq = fmaf(hi, Wq[i], aq);
        ak = fmaf(hi, Wk[i], ak);
        av = fmaf(hi, Wv[i], av);
        if (tl) at = fmaf(hi, Wt[i], at);
    }
    aq = fmaf(cr, Wq[32], aq); aq = fmaf(cc, Wq[33], aq);
    ak = fmaf(cr, Wk[32], ak); ak = fmaf(cc, Wk[33], ak);
    av = fmaf(cr, Wv[32], av); av = fmaf(cc, Wv[33], av);
    if (tl) { at = fmaf(cr, Wt[32], at); at = fmaf(cc, Wt[33], at); }

    float* qb = g_q[buf] + n * KSTR;
    float* kb = g_k[buf] + n * KSTR;
    float* vb = g_v[buf] + n * KSTR;
    __stcg(qb + lane, aq);
    __stcg(kb + lane, ak);
    __stcg(vb + lane, av);
    if (tl) {
        float* dst = (d < 2 ? qb : (d < 4 ? kb : vb)) + 32 + (d & 1);
        __stcg(dst, at);
    }
    return hp;
}

// Phase B: 9-neighbor attention + out-proj + fcsa residual + fc2 + layernorm.
__device__ __forceinline__ void phaseB(const Smem& sm, int n, int buf, float hp,
                                       float* h_out, float* pred_out,
                                       float* __restrict__ out_t, int lane) {
    int p = n & (P_GRID - 1);
    int b_off = n - p;
    int r = p >> 6, c = p & 63;
    int rs = (r == 0) - (r == 63);
    int cs = (c == 0) - (c == 63);
    int base = b_off + p + rs * 64 + cs;   // row of shifted-center slot (l=4)

    const float* qrow = g_q[buf] + base * KSTR;
    float qj = __ldcg(qrow + lane);
    float qt = (lane < 2) ? __ldcg(qrow + 32 + lane) : 0.0f;
    float q32 = __shfl_sync(FULLMASK, qt, 0);
    float q33 = __shfl_sync(FULLMASK, qt, 1);

    const int OFF[9] = {-65, -64, -63, -1, 0, 1, 63, 64, 65};
    float s[9];
#pragma unroll
    for (int l = 0; l < 9; l++) {
        const float* kr = g_k[buf] + (base + OFF[l]) * KSTR;
        float pr = qj * __ldcg(kr + lane);
        if (lane < 2) {
            float kt = __ldcg(kr + 32 + lane);
            pr = fmaf((lane == 0) ? q32 : q33, kt, pr);
        }
        s[l] = warp_sum(pr);
    }
    const float SCALE = 0.17149858514250882f;  // 1/sqrt(34)
    float mx = s[0];
#pragma unroll
    for (int l = 1; l < 9; l++) mx = fmaxf(mx, s[l]);
    float wsum = 0.0f;
#pragma unroll
    for (int l = 0; l < 9; l++) { s[l] = __expf((s[l] - mx) * SCALE); wsum += s[l]; }
    float rinv = 1.0f / wsum;

    float oj = 0.0f, ot = 0.0f;
#pragma unroll
    for (int l = 0; l < 9; l++) {
        const float* vr = g_v[buf] + (base + OFF[l]) * KSTR;
        oj = fmaf(s[l], __ldcg(vr + lane), oj);
        if (lane < 2) ot = fmaf(s[l], __ldcg(vr + 32 + lane), ot);
    }
    oj *= rinv; ot *= rinv;
    float o32 = __shfl_sync(FULLMASK, ot, 0);
    float o33 = __shfl_sync(FULLMASK, ot, 1);

    // out-projection: 34 -> 34 (tail rows 32,33 on lanes 30,31)
    bool t2 = (lane >= 30);
    int trow2 = t2 ? (32 + (lane - 30)) : 0;
    float ao = sm.b_out[lane];
    float aot = t2 ? sm.b_out[trow2] : 0.0f;
    const float* Wo  = sm.Wout + lane * 35;
    const float* Wot = sm.Wout + trow2 * 35;
#pragma unroll
    for (int i = 0; i < 32; i++) {
        float oi = __shfl_sync(FULLMASK, oj, i);
        ao = fmaf(oi, Wo[i], ao);
        if (t2) aot = fmaf(oi, Wot[i], aot);
    }
    ao = fmaf(o32, Wo[32], ao); ao = fmaf(o33, Wo[33], ao);
    if (t2) { aot = fmaf(o32, Wot[32], aot); aot = fmaf(o33, Wot[33], aot); }
    float ao32 = __shfl_sync(FULLMASK, aot, 30);
    float ao33 = __shfl_sync(FULLMASK, aot, 31);

    // fcsa residual: h = h_pre + ao @ W_fcsa^T + b_fcsa
    float dh = sm.b_sa[lane];
    const float* Ws = sm.Wsa + lane * 35;
#pragma unroll
    for (int i = 0; i < 32; i++) {
        float ai = __shfl_sync(FULLMASK, ao, i);
        dh = fmaf(ai, Ws[i], dh);
    }
    dh = fmaf(ao32, Ws[32], dh);
    dh = fmaf(ao33, Ws[33], dh);
    float h = hp + dh;

    // fc2 + layernorm
    float y = sm.b_f2[lane];
    const float* Wf = sm.Wf2 + lane * 33;
#pragma unroll
    for (int i = 0; i < 32; i++) {
        float hi = __shfl_sync(FULLMASK, h, i);
        y = fmaf(hi, Wf[i], y);
    }
    float mu = warp_sum(y) * (1.0f / 32.0f);
    float dv = y - mu;
    float var = warp_sum(dv * dv) * (1.0f / 32.0f);
    float pred = dv * rsqrtf(var + 1e-5f) * sm.lng[lane] + sm.lnb[lane];

    out_t[n * HDIM + lane] = pred;
    *h_out = h;
    *pred_out = pred;
}

__global__ void __launch_bounds__(NTHREADS, 1)
rnn_persistent_kernel(const float* __restrict__ x,
                      const float* __restrict__ Wx, const float* __restrict__ bx,
                      const float* __restrict__ Wh, const float* __restrict__ bh,
                      const float* __restrict__ Wf2, const float* __restrict__ bf2,
                      const float* __restrict__ lng, const float* __restrict__ lnb,
                      const float* __restrict__ Wsa, const float* __restrict__ bsa,
                      const float* __restrict__ Win, const float* __restrict__ bin,
                      const float* __restrict__ Wout, const float* __restrict__ bout,
                      float* __restrict__ out) {
    __shared__ Smem sm;
    int tid = threadIdx.x;

    for (int idx = tid; idx < 32 * 32; idx += NTHREADS) {
        int rr = idx >> 5, ii = idx & 31;
        sm.Wx[rr * 33 + ii]  = Wx[idx];
        sm.Wh[rr * 33 + ii]  = Wh[idx];
        sm.Wf2[rr * 33 + ii] = Wf2[idx];
    }
    for (int idx = tid; idx < 32 * 34; idx += NTHREADS) {
        int rr = idx / 34, ii = idx % 34;
        sm.Wsa[rr * 35 + ii] = Wsa[idx];
    }
    for (int idx = tid; idx < 34 * 34; idx += NTHREADS) {
        int rr = idx / 34, ii = idx % 34;
        sm.Wout[rr * 35 + ii] = Wout[idx];
    }
    for (int idx = tid; idx < 102 * 34; idx += NTHREADS) {
        int rr = idx / 34, ii = idx % 34;
        sm.Win[rr * 35 + ii] = Win[idx];
    }
    if (tid < 32) {
        sm.b_h[tid]  = bx[tid] + bh[tid];
        sm.b_sa[tid] = bsa[tid];
        sm.b_f2[tid] = bf2[tid];
        sm.lng[tid]  = lng[tid];
        sm.lnb[tid]  = lnb[tid];
    }
    for (int idx = tid; idx < 102; idx += NTHREADS) sm.b_in[idx] = bin[idx];
    if (tid < 34) sm.b_out[tid] = bout[tid];
    __syncthreads();

    int wid = tid >> 5, lane = tid & 31;
    int gw = blockIdx.x * NWARPS + wid;
    int n0 = gw * 2;
    bool active = (n0 < NROWS);

    float h[2]    = {0.0f, 0.0f};
    float hp[2]   = {0.0f, 0.0f};
    float pred[2] = {0.0f, 0.0f};

    // Phase A for t = 0 (input = x[0], h = 0)
    if (active) {
#pragma unroll
        for (int rr = 0; rr < 2; rr++) {
            float xin = x[(n0 + rr) * HDIM + lane];
            hp[rr] = phaseA(sm, n0 + rr, 0, xin, h[rr], lane);
        }
    }

    for (int t = 0; t < T_TOTAL; t++) {
        grid_barrier();   // q/k/v(t) of all rows now visible
        int buf = t & 1;
        if (active) {
            float* out_t = out + (size_t)t * NROWS * HDIM;
#pragma unroll
            for (int rr = 0; rr < 2; rr++) {
                phaseB(sm, n0 + rr, buf, hp[rr], &h[rr], &pred[rr], out_t, lane);
            }
            if (t < T_TOTAL - 1) {
#pragma unroll
                for (int rr = 0; rr < 2; rr++) {
                    float xin = (t + 1 < T_OBS)
                                    ? x[(size_t)(t + 1) * NROWS * HDIM + (n0 + rr) * HDIM + lane]
                                    : pred[rr];
                    hp[rr] = phaseA(sm, n0 + rr, buf ^ 1, xin, h[rr], lane);
                }
            }
        }
    }
}

extern "C" void kernel_launch(void* const* d_in, const int* in_sizes, int n_in,
                              void* d_out, int out_size) {
    (void)in_sizes; (void)n_in; (void)out_size;
    rnn_persistent_kernel<<<NBLOCKS, NTHREADS>>>(
        (const float*)d_in[0],   // x
        (const float*)d_in[1],   // W_x2h
        (const float*)d_in[2],   // b_x2h
        (const float*)d_in[3],   // W_h2h
        (const float*)d_in[4],   // b_h2h
        (const float*)d_in[5],   // W_fc2
        (const float*)d_in[6],   // b_fc2
        (const float*)d_in[7],   // ln_g
        (const float*)d_in[8],   // ln_b
        (const float*)d_in[9],   // W_fcsa
        (const float*)d_in[10],  // b_fcsa
        (const float*)d_in[11],  // W_in
        (const float*)d_in[12],  // b_in
        (const float*)d_in[13],  // W_out
        (const float*)d_in[14],  // b_out
        (float*)d_out);
}